// round 7
// baseline (speedup 1.0000x reference)
#include <cuda_runtime.h>
#include <cstddef>

#define BATCH   8
#define T_LEN   4096
#define HC      256
#define HD      512
#define NROWS   (BATCH * T_LEN)
#define CHUNK   128
#define NCHUNK  (T_LEN / CHUNK)        // 32
#define NTASKS  (BATCH * NCHUNK * 8)   // 2048: (b,c) x 8 row-blocks of 16

__device__ float g_wx0[NROWS * HD];
__device__ float g_h0 [NROWS * HD];
__device__ float g_wx1[NROWS * HD];
// [0,64): h0 chunk progress per (b,rank); [64,320): wx1 per-(b,c) count (target 8); [320]: task ctr
__device__ unsigned g_flags[328];

#define BAR_SCAN() asm volatile("bar.sync 1, 256;" ::: "memory")
#define BAR_GEMM() asm volatile("bar.sync 2, 64;"  ::: "memory")

// ---------------------------------------------------------------- helpers
static __device__ __forceinline__ unsigned su32(const void* p) {
    return (unsigned)__cvta_generic_to_shared(p);
}
static __device__ __forceinline__ unsigned long long packf2(float lo, float hi) {
    unsigned long long r;
    asm("mov.b64 %0, {%1, %2};" : "=l"(r) : "f"(lo), "f"(hi));
    return r;
}
static __device__ __forceinline__ void unpackf2(unsigned long long v, float& lo, float& hi) {
    asm("mov.b64 {%0, %1}, %2;" : "=f"(lo), "=f"(hi) : "l"(v));
}
static __device__ __forceinline__ float fast_tanh(float x) {
    float e = __expf(2.0f * x);
    return 1.0f - __fdividef(2.0f, e + 1.0f);
}
static __device__ __forceinline__ void mbar_wait(unsigned addr, unsigned parity) {
    asm volatile(
        "{\n\t.reg .pred P;\n"
        "LW_%=:\n\t"
        "mbarrier.try_wait.parity.acquire.cluster.shared::cta.b64 P, [%0], %1, 0x989680;\n\t"
        "@P bra LD_%=;\n\t"
        "bra LW_%=;\n"
        "LD_%=:\n\t}"
        :: "r"(addr), "r"(parity) : "memory");
}
static __device__ __forceinline__ unsigned ld_acq(const unsigned* p) {
    unsigned v;
    asm volatile("ld.acquire.gpu.global.u32 %0, [%1];" : "=r"(v) : "l"(p) : "memory");
    return v;
}
static __device__ __forceinline__ void st_rel(unsigned* p, unsigned v) {
    asm volatile("st.release.gpu.global.u32 [%0], %1;" :: "l"(p), "r"(v) : "memory");
}
static __device__ __forceinline__ void red_add_rel(unsigned* p, unsigned v) {
    asm volatile("red.add.release.gpu.global.u32 [%0], %1;" :: "l"(p), "r"(v) : "memory");
}

// ---------------------------------------------------------------------------
// Projection GEMM (layer 0): full-chip, Y = X @ Mw0 + b0  (unchanged)
// ---------------------------------------------------------------------------
__global__ __launch_bounds__(256) void proj_kernel(
    const float* __restrict__ X,
    const float* __restrict__ wr, const float* __restrict__ wi,
    const float* __restrict__ br, const float* __restrict__ bi,
    float* __restrict__ Y)
{
    __shared__ float As[16][132];
    __shared__ float Bs[16][132];

    const int bm  = blockIdx.x * 128;
    const int bn  = blockIdx.y * 128;
    const int tid = threadIdx.x;
    const int tx  = tid & 15;
    const int ty  = tid >> 4;
    const int am  = tid >> 1;
    const int ak  = (tid & 1) * 8;
    const int bk  = tid >> 4;
    const int bj  = (tid & 15) * 8;
    const bool jhi = (bn + bj) >= 256;
    const int  jj  = (bn + bj) & 255;

    float acc[8][8];
#pragma unroll
    for (int r = 0; r < 8; ++r)
#pragma unroll
        for (int c = 0; c < 8; ++c) acc[r][c] = 0.f;

    for (int k0 = 0; k0 < HD; k0 += 16) {
        const float* xrow = X + (size_t)(bm + am) * HD + k0 + ak;
        float4 a0 = *(const float4*)(xrow);
        float4 a1 = *(const float4*)(xrow + 4);
        As[ak + 0][am] = a0.x; As[ak + 1][am] = a0.y;
        As[ak + 2][am] = a0.z; As[ak + 3][am] = a0.w;
        As[ak + 4][am] = a1.x; As[ak + 5][am] = a1.y;
        As[ak + 6][am] = a1.z; As[ak + 7][am] = a1.w;
        {
            int k = k0 + bk;
            float4 b0, b1;
            if (k < 256) {
                const float* src = (jhi ? wi : wr) + (size_t)k * 256 + jj;
                b0 = *(const float4*)(src);
                b1 = *(const float4*)(src + 4);
            } else {
                const float* src = (jhi ? wr : wi) + (size_t)(k - 256) * 256 + jj;
                b0 = *(const float4*)(src);
                b1 = *(const float4*)(src + 4);
                if (!jhi) {
                    b0.x = -b0.x; b0.y = -b0.y; b0.z = -b0.z; b0.w = -b0.w;
                    b1.x = -b1.x; b1.y = -b1.y; b1.z = -b1.z; b1.w = -b1.w;
                }
            }
            *(float4*)&Bs[bk][bj]     = b0;
            *(float4*)&Bs[bk][bj + 4] = b1;
        }
        __syncthreads();
#pragma unroll
        for (int kk = 0; kk < 16; ++kk) {
            float4 av0 = *(const float4*)&As[kk][ty * 8];
            float4 av1 = *(const float4*)&As[kk][ty * 8 + 4];
            float4 bv0 = *(const float4*)&Bs[kk][tx * 8];
            float4 bv1 = *(const float4*)&Bs[kk][tx * 8 + 4];
            float a[8] = {av0.x, av0.y, av0.z, av0.w, av1.x, av1.y, av1.z, av1.w};
            float b[8] = {bv0.x, bv0.y, bv0.z, bv0.w, bv1.x, bv1.y, bv1.z, bv1.w};
#pragma unroll
            for (int r = 0; r < 8; ++r)
#pragma unroll
                for (int c = 0; c < 8; ++c)
                    acc[r][c] = fmaf(a[r], b[c], acc[r][c]);
        }
        __syncthreads();
    }

    const int col0 = bn + tx * 8;
    float bias[8];
#pragma unroll
    for (int c = 0; c < 8; ++c) {
        int j = col0 + c;
        bias[c] = (j < 256) ? br[j] : bi[j - 256];
    }
#pragma unroll
    for (int r = 0; r < 8; ++r) {
        float* yrow = Y + (size_t)(bm + ty * 8 + r) * HD + col0;
        *(float4*)(yrow)     = make_float4(acc[r][0]+bias[0], acc[r][1]+bias[1],
                                           acc[r][2]+bias[2], acc[r][3]+bias[3]);
        *(float4*)(yrow + 4) = make_float4(acc[r][4]+bias[4], acc[r][5]+bias[5],
                                           acc[r][6]+bias[6], acc[r][7]+bias[7]);
    }
}

// ---------------------------------------------------------------------------
struct SmemScan {
    float hbuf[2][HD];
    float stage[64];
    unsigned long long mbar[2];
};
struct SmemGemm {          // BM=16, BN=128, BK=16 tiles for the 2-warp GEMM
    float As[16][20];
    float Bs[16][132];
    unsigned task;
};

// Scan: threads 64..319 (s_tid 0..255), warps 2..9. Identical dataflow to R4/R6.
static __device__ void scan_body(
    SmemScan& sm, int s_tid,
    const float* wx, const float* ur, const float* ui,
    const float* ubr, const float* ubi,
    float* out, int b, bool publish, bool gate, unsigned* flags)
{
    unsigned rank;
    asm("mov.u32 %0, %%cluster_ctarank;" : "=r"(rank));
    const int lane = s_tid & 31;
    const int jg   = s_tid >> 4;
    const int kg   = s_tid & 15;
    const int j0   = (int)rank * 64 + jg * 4;
    const int jj   = j0 & 255;
    const bool jhi = j0 >= 256;

    const unsigned hb_u32 = su32(&sm.hbuf[0][0]);
    const unsigned st_u32 = su32(&sm.stage[0]);
    const unsigned mb_u32 = su32(&sm.mbar[0]);

    unsigned dsth[8], dstm[8];
#pragma unroll
    for (int d = 0; d < 8; ++d) {
        asm("mapa.shared::cluster.u32 %0, %1, %2;" : "=r"(dsth[d]) : "r"(hb_u32), "r"(d));
        asm("mapa.shared::cluster.u32 %0, %1, %2;" : "=r"(dstm[d]) : "r"(mb_u32), "r"(d));
    }
    const unsigned my_off = (unsigned)(rank * 256);

    unsigned long long w2[4][16];
#pragma unroll
    for (int q = 0; q < 8; ++q) {
        const int k = q * 64 + kg * 4;
        float4 r0, r1, r2, r3;
        if (k < 256) {
            const float* src = (jhi ? ui : ur) + (size_t)k * 256 + jj;
            r0 = *(const float4*)(src);
            r1 = *(const float4*)(src + 256);
            r2 = *(const float4*)(src + 512);
            r3 = *(const float4*)(src + 768);
        } else {
            const float* src = (jhi ? ur : ui) + (size_t)(k - 256) * 256 + jj;
            const float s = jhi ? 1.f : -1.f;
            r0 = *(const float4*)(src);
            r1 = *(const float4*)(src + 256);
            r2 = *(const float4*)(src + 512);
            r3 = *(const float4*)(src + 768);
            r0.x *= s; r0.y *= s; r0.z *= s; r0.w *= s;
            r1.x *= s; r1.y *= s; r1.z *= s; r1.w *= s;
            r2.x *= s; r2.y *= s; r2.z *= s; r2.w *= s;
            r3.x *= s; r3.y *= s; r3.z *= s; r3.w *= s;
        }
        w2[0][2*q]   = packf2(r0.x, r1.x);
        w2[1][2*q]   = packf2(r0.y, r1.y);
        w2[2][2*q]   = packf2(r0.z, r1.z);
        w2[3][2*q]   = packf2(r0.w, r1.w);
        w2[0][2*q+1] = packf2(r2.x, r3.x);
        w2[1][2*q+1] = packf2(r2.y, r3.y);
        w2[2][2*q+1] = packf2(r2.z, r3.z);
        w2[3][2*q+1] = packf2(r2.w, r3.w);
    }
    const float4 ub = jhi ? *(const float4*)(ubi + jj)
                          : *(const float4*)(ubr + jj);

    const float* wx_b  = wx  + (size_t)b * (T_LEN * HD);
    float*       out_b = out + (size_t)b * (T_LEN * HD);
    unsigned* wx_ready = flags + 64 + b * NCHUNK;
    unsigned* my_flag  = flags + b * 8 + rank;

    if (gate) {
        if (s_tid == 0) {
            while (ld_acq(wx_ready) < 8u) __nanosleep(128);
        }
        BAR_SCAN();
    }

    // t = 0
    {
        float4 wv = __ldcg((const float4*)(wx_b + j0));
        float4 yv;
        yv.x = fast_tanh(wv.x + ub.x);
        yv.y = fast_tanh(wv.y + ub.y);
        yv.z = fast_tanh(wv.z + ub.z);
        yv.w = fast_tanh(wv.w + ub.w);
        if ((lane & 15) == 0) *(float4*)&sm.stage[jg * 4] = yv;
        if ((lane & 15) == 8) *(float4*)(out_b + j0) = yv;
        BAR_SCAN();
        if (s_tid == 0) {
            asm volatile("fence.proxy.async.shared::cta;" ::: "memory");
#pragma unroll
            for (int d = 0; d < 8; ++d) {
                asm volatile(
                    "cp.async.bulk.shared::cluster.shared::cta.mbarrier::complete_tx::bytes "
                    "[%0], [%1], %2, [%3];"
                    :: "r"(dsth[d] + my_off), "r"(st_u32), "r"(256u), "r"(dstm[d])
                    : "memory");
            }
        }
    }

    for (int t = 1; t < T_LEN; ++t) {
        if (gate && (t & (CHUNK - 1)) == 0) {
            if (s_tid == 0) {
                const unsigned c = (unsigned)(t >> 7);
                while (ld_acq(wx_ready + c) < 8u) __nanosleep(128);
            }
            BAR_SCAN();
        }

        float4 wv = __ldcg((const float4*)(wx_b + (size_t)t * HD + j0));

        const int use  = t - 1;
        const int rbuf = use & 1;
        mbar_wait(mb_u32 + rbuf * 8, (unsigned)((use >> 1) & 1));

        if (s_tid == 0) {
            asm volatile("mbarrier.arrive.expect_tx.shared::cta.b64 _, [%0], %1;"
                         :: "r"(mb_u32 + rbuf * 8), "r"(2048u) : "memory");
        }

        unsigned long long h2[16];
        const float* hp = &sm.hbuf[rbuf][0];
#pragma unroll
        for (int q = 0; q < 8; ++q) {
            ulonglong2 v = *(const ulonglong2*)(hp + q * 64 + kg * 4);
            h2[2*q]   = v.x;
            h2[2*q+1] = v.y;
        }

        unsigned long long acc0 = 0, acc1 = 0, acc2 = 0, acc3 = 0;
#pragma unroll
        for (int q = 0; q < 16; ++q) {
            asm("fma.rn.f32x2 %0, %1, %2, %0;" : "+l"(acc0) : "l"(h2[q]), "l"(w2[0][q]));
            asm("fma.rn.f32x2 %0, %1, %2, %0;" : "+l"(acc1) : "l"(h2[q]), "l"(w2[1][q]));
            asm("fma.rn.f32x2 %0, %1, %2, %0;" : "+l"(acc2) : "l"(h2[q]), "l"(w2[2][q]));
            asm("fma.rn.f32x2 %0, %1, %2, %0;" : "+l"(acc3) : "l"(h2[q]), "l"(w2[3][q]));
        }
        float a0, a1, a2, a3, hq;
        unpackf2(acc0, a0, hq); a0 += hq;
        unpackf2(acc1, a1, hq); a1 += hq;
        unpackf2(acc2, a2, hq); a2 += hq;
        unpackf2(acc3, a3, hq); a3 += hq;
#pragma unroll
        for (int off = 1; off < 16; off <<= 1) {
            a0 += __shfl_xor_sync(0xffffffffu, a0, off);
            a1 += __shfl_xor_sync(0xffffffffu, a1, off);
            a2 += __shfl_xor_sync(0xffffffffu, a2, off);
            a3 += __shfl_xor_sync(0xffffffffu, a3, off);
        }

        float4 yv;
        yv.x = fast_tanh(wv.x + ub.x + a0);
        yv.y = fast_tanh(wv.y + ub.y + a1);
        yv.z = fast_tanh(wv.z + ub.z + a2);
        yv.w = fast_tanh(wv.w + ub.w + a3);

        if ((lane & 15) == 0) *(float4*)&sm.stage[jg * 4] = yv;
        if ((lane & 15) == 8) *(float4*)(out_b + (size_t)t * HD + j0) = yv;

        if (t < T_LEN - 1) {
            BAR_SCAN();
            if (s_tid == 0) {
                const unsigned boff = (unsigned)((t & 1) * 2048) + my_off;
                const unsigned moff = (unsigned)((t & 1) * 8);
                asm volatile("fence.proxy.async.shared::cta;" ::: "memory");
#pragma unroll
                for (int d = 0; d < 8; ++d) {
                    asm volatile(
                        "cp.async.bulk.shared::cluster.shared::cta.mbarrier::complete_tx::bytes "
                        "[%0], [%1], %2, [%3];"
                        :: "r"(dsth[d] + boff), "r"(st_u32), "r"(256u), "r"(dstm[d] + moff)
                        : "memory");
                }
                if (publish && (t & (CHUNK - 1)) == (CHUNK - 1)) {
                    st_rel(my_flag, (unsigned)((t >> 7) + 1));
                }
            }
        }
    }

    if (publish) {
        BAR_SCAN();
        if (s_tid == 0) st_rel(my_flag, (unsigned)NCHUNK);
    }
}

// Background GEMM: threads 0..63 (warps 0,1 — lowest arbiter priority).
// Task = (b, c, rb): wx1[b, c*128 + rb*16 .. +15, 0..511] = h0 @ Mw1 + b1.
static __device__ void gemm_pool(
    SmemGemm& sg,
    const float* X, const float* wr, const float* wi,
    const float* br, const float* bi, float* Y, unsigned* flags)
{
    const int gt = threadIdx.x;        // 0..63
    const int tx = gt & 15;            // 16 col groups of 8
    const int ty = (gt >> 4) & 3;      // 4 row groups of 4
    const int am = gt & 15;            // A-load: row within 16
    const int ak = (gt >> 4) * 4;      // A-load: 4 k's
    const int kb = gt & 15;            // B-load: k row
    const int jb = (gt >> 4) * 32;     // B-load: 32-col block
    unsigned* cnt = flags + 320;

    for (;;) {
        BAR_GEMM();
        if (gt == 0) sg.task = atomicAdd(cnt, 1u);
        BAR_GEMM();
        const unsigned id = sg.task;
        if (id >= (unsigned)NTASKS) break;

        const int c  = (int)(id >> 6);
        const int b  = (int)((id >> 3) & 7);
        const int rb = (int)(id & 7);

        if (gt < 8) {
            const unsigned* f = flags + b * 8 + gt;
            while (ld_acq(f) < (unsigned)(c + 1)) __nanosleep(256);
        }
        BAR_GEMM();

        const int bm = b * T_LEN + c * CHUNK + rb * 16;

        for (int bnb = 0; bnb < 4; ++bnb) {
            const int bn   = bnb * 128;
            const bool jhi = (bn + jb) >= 256;
            const int  jj  = (bn + jb) & 255;

            float acc[4][8];
#pragma unroll
            for (int r = 0; r < 4; ++r)
#pragma unroll
                for (int cc = 0; cc < 8; ++cc) acc[r][cc] = 0.f;

            for (int k0 = 0; k0 < HD; k0 += 16) {
                // A tile: 16 rows x 16 k
                {
                    float4 a = __ldcg((const float4*)(X + (size_t)(bm + am) * HD + k0 + ak));
                    sg.As[ak + 0][am] = a.x;
                    sg.As[ak + 1][am] = a.y;
                    sg.As[ak + 2][am] = a.z;
                    sg.As[ak + 3][am] = a.w;
                }
                // B tile: 16 k x 128 j (each thread: 32 cols of one k row)
                {
                    const int k = k0 + kb;
                    const float* src;
                    float sgn = 1.f;
                    if (k < 256) {
                        src = (jhi ? wi : wr) + (size_t)k * 256 + jj;
                    } else {
                        src = (jhi ? wr : wi) + (size_t)(k - 256) * 256 + jj;
                        if (!jhi) sgn = -1.f;
                    }
#pragma unroll
                    for (int q = 0; q < 8; ++q) {
                        float4 v = *(const float4*)(src + q * 4);
                        v.x *= sgn; v.y *= sgn; v.z *= sgn; v.w *= sgn;
                        *(float4*)&sg.Bs[kb][jb + q * 4] = v;
                    }
                }
                BAR_GEMM();
#pragma unroll
                for (int kk = 0; kk < 16; ++kk) {
                    float a[4];
                    a[0] = sg.As[kk][ty * 4 + 0];
                    a[1] = sg.As[kk][ty * 4 + 1];
                    a[2] = sg.As[kk][ty * 4 + 2];
                    a[3] = sg.As[kk][ty * 4 + 3];
                    float4 bv0 = *(const float4*)&sg.Bs[kk][tx * 8];
                    float4 bv1 = *(const float4*)&sg.Bs[kk][tx * 8 + 4];
                    float bb[8] = {bv0.x, bv0.y, bv0.z, bv0.w, bv1.x, bv1.y, bv1.z, bv1.w};
#pragma unroll
                    for (int r = 0; r < 4; ++r)
#pragma unroll
                        for (int cc = 0; cc < 8; ++cc)
                            acc[r][cc] = fmaf(a[r], bb[cc], acc[r][cc]);
                }
                BAR_GEMM();
            }

            const int col0 = bn + tx * 8;
            float bias[8];
#pragma unroll
            for (int cc = 0; cc < 8; ++cc) {
                int j = col0 + cc;
                bias[cc] = (j < 256) ? br[j] : bi[j - 256];
            }
#pragma unroll
            for (int r = 0; r < 4; ++r) {
                float* yrow = Y + (size_t)(bm + ty * 4 + r) * HD + col0;
                *(float4*)(yrow)     = make_float4(acc[r][0]+bias[0], acc[r][1]+bias[1],
                                                   acc[r][2]+bias[2], acc[r][3]+bias[3]);
                *(float4*)(yrow + 4) = make_float4(acc[r][4]+bias[4], acc[r][5]+bias[5],
                                                   acc[r][6]+bias[6], acc[r][7]+bias[7]);
            }
        }

        BAR_GEMM();
        if (gt == 0) red_add_rel(flags + 64 + b * NCHUNK + c, 1u);
    }
}

__global__ void __cluster_dims__(8, 1, 1) __launch_bounds__(320, 1)
fused_kernel(const float* __restrict__ wx0,
             const float* __restrict__ l0_ur, const float* __restrict__ l0_ui,
             const float* __restrict__ l0_ubr, const float* __restrict__ l0_ubi,
             const float* __restrict__ l1_wr, const float* __restrict__ l1_wi,
             const float* __restrict__ l1_wbr, const float* __restrict__ l1_wbi,
             const float* __restrict__ l1_ur, const float* __restrict__ l1_ui,
             const float* __restrict__ l1_ubr, const float* __restrict__ l1_ubi,
             float* h0, float* wx1, float* out, unsigned* flags)
{
    __shared__ __align__(16) SmemScan ss;
    __shared__ __align__(16) SmemGemm sg;

    const int cl  = blockIdx.x >> 3;
    const int tid = threadIdx.x;

    // mbarrier init + arm (scan's s_tid 0 == tid 64)
    if (tid == 64) {
        const unsigned mb = su32(&ss.mbar[0]);
        asm volatile("mbarrier.init.shared.b64 [%0], %1;" :: "r"(mb),     "r"(1u) : "memory");
        asm volatile("mbarrier.init.shared.b64 [%0], %1;" :: "r"(mb + 8), "r"(1u) : "memory");
        asm volatile("mbarrier.arrive.expect_tx.shared::cta.b64 _, [%0], %1;"
                     :: "r"(mb),     "r"(2048u) : "memory");
        asm volatile("mbarrier.arrive.expect_tx.shared::cta.b64 _, [%0], %1;"
                     :: "r"(mb + 8), "r"(2048u) : "memory");
    }
    __syncthreads();
    asm volatile("barrier.cluster.arrive.aligned;" ::: "memory");
    asm volatile("barrier.cluster.wait.aligned;"   ::: "memory");

    if (tid >= 64) {
        if (cl < 8) {
            scan_body(ss, tid - 64, wx0, l0_ur, l0_ui, l0_ubr, l0_ubi,
                      h0, cl, /*publish=*/true, /*gate=*/false, flags);
        } else {
            scan_body(ss, tid - 64, wx1, l1_ur, l1_ui, l1_ubr, l1_ubi,
                      out, cl - 8, /*publish=*/false, /*gate=*/true, flags);
        }
    } else {
        gemm_pool(sg, h0, l1_wr, l1_wi, l1_wbr, l1_wbi, wx1, flags);
    }

    // final cluster barrier (non-aligned: reached from divergent paths)
    asm volatile("barrier.cluster.arrive;" ::: "memory");
    asm volatile("barrier.cluster.wait;"   ::: "memory");
}

// ---------------------------------------------------------------------------
extern "C" void kernel_launch(void* const* d_in, const int* in_sizes, int n_in,
                              void* d_out, int out_size)
{
    const float* x      = (const float*)d_in[0];
    const float* l0_wr  = (const float*)d_in[1];
    const float* l0_wi  = (const float*)d_in[2];
    const float* l0_wbr = (const float*)d_in[3];
    const float* l0_wbi = (const float*)d_in[4];
    const float* l0_ur  = (const float*)d_in[5];
    const float* l0_ui  = (const float*)d_in[6];
    const float* l0_ubr = (const float*)d_in[7];
    const float* l0_ubi = (const float*)d_in[8];
    const float* l1_wr  = (const float*)d_in[9];
    const float* l1_wi  = (const float*)d_in[10];
    const float* l1_wbr = (const float*)d_in[11];
    const float* l1_wbi = (const float*)d_in[12];
    const float* l1_ur  = (const float*)d_in[13];
    const float* l1_ui  = (const float*)d_in[14];
    const float* l1_ubr = (const float*)d_in[15];
    const float* l1_ubi = (const float*)d_in[16];

    float* out = (float*)d_out;

    void *p_wx0_v = nullptr, *p_h0_v = nullptr, *p_wx1_v = nullptr, *p_fl_v = nullptr;
    cudaGetSymbolAddress(&p_wx0_v, g_wx0);
    cudaGetSymbolAddress(&p_h0_v,  g_h0);
    cudaGetSymbolAddress(&p_wx1_v, g_wx1);
    cudaGetSymbolAddress(&p_fl_v,  g_flags);
    float* p_wx0 = (float*)p_wx0_v;
    float* p_h0  = (float*)p_h0_v;
    float* p_wx1 = (float*)p_wx1_v;
    unsigned* p_fl = (unsigned*)p_fl_v;

    cudaMemsetAsync(p_fl, 0, sizeof(unsigned) * 328);

    dim3 pgrid(NROWS / 128, HD / 128);
    proj_kernel<<<pgrid, 256>>>(x, l0_wr, l0_wi, l0_wbr, l0_wbi, p_wx0);

    // 128 CTAs = 16 clusters of 8; 320 threads = 2 GEMM warps + 8 scan warps
    fused_kernel<<<128, 320>>>(p_wx0,
                               l0_ur, l0_ui, l0_ubr, l0_ubi,
                               l1_wr, l1_wi, l1_wbr, l1_wbi,
                               l1_ur, l1_ui, l1_ubr, l1_ubi,
                               p_h0, p_wx1, out, p_fl);
}

// round 8
// speedup vs baseline: 1.0653x; 1.0653x over previous
#include <cuda_runtime.h>
#include <cstddef>

#define BATCH   8
#define T_LEN   4096
#define HC      256
#define HD      512
#define NROWS   (BATCH * T_LEN)

__device__ float g_wx[NROWS * HD];   // input-projection output
__device__ float g_h0[NROWS * HD];   // layer-0 hidden states

// ---------------------------------------------------------------- helpers
static __device__ __forceinline__ unsigned su32(const void* p) {
    return (unsigned)__cvta_generic_to_shared(p);
}
static __device__ __forceinline__ unsigned long long packf2(float lo, float hi) {
    unsigned long long r;
    asm("mov.b64 %0, {%1, %2};" : "=l"(r) : "f"(lo), "f"(hi));
    return r;
}
static __device__ __forceinline__ void unpackf2(unsigned long long v, float& lo, float& hi) {
    asm("mov.b64 {%0, %1}, %2;" : "=f"(lo), "=f"(hi) : "l"(v));
}
static __device__ __forceinline__ float fast_tanh(float x) {
    float e = __expf(2.0f * x);
    return 1.0f - __fdividef(2.0f, e + 1.0f);
}
static __device__ __forceinline__ void mbar_wait(unsigned addr, unsigned parity) {
    asm volatile(
        "{\n\t.reg .pred P;\n"
        "LW_%=:\n\t"
        "mbarrier.try_wait.parity.acquire.cluster.shared::cta.b64 P, [%0], %1, 0x989680;\n\t"
        "@P bra LD_%=;\n\t"
        "bra LW_%=;\n"
        "LD_%=:\n\t}"
        :: "r"(addr), "r"(parity) : "memory");
}

// ---------------------------------------------------------------------------
// Projection GEMM (unchanged from R4): Y[N,512] = X[N,512] @ Mw[512,512] + b
// ---------------------------------------------------------------------------
__global__ __launch_bounds__(256) void proj_kernel(
    const float* __restrict__ X,
    const float* __restrict__ wr, const float* __restrict__ wi,
    const float* __restrict__ br, const float* __restrict__ bi,
    float* __restrict__ Y)
{
    __shared__ float As[16][132];
    __shared__ float Bs[16][132];

    const int bm  = blockIdx.x * 128;
    const int bn  = blockIdx.y * 128;
    const int tid = threadIdx.x;
    const int tx  = tid & 15;
    const int ty  = tid >> 4;
    const int am  = tid >> 1;
    const int ak  = (tid & 1) * 8;
    const int bk  = tid >> 4;
    const int bj  = (tid & 15) * 8;
    const bool jhi = (bn + bj) >= 256;
    const int  jj  = (bn + bj) & 255;

    float acc[8][8];
#pragma unroll
    for (int r = 0; r < 8; ++r)
#pragma unroll
        for (int c = 0; c < 8; ++c) acc[r][c] = 0.f;

    for (int k0 = 0; k0 < HD; k0 += 16) {
        const float* xrow = X + (size_t)(bm + am) * HD + k0 + ak;
        float4 a0 = *(const float4*)(xrow);
        float4 a1 = *(const float4*)(xrow + 4);
        As[ak + 0][am] = a0.x; As[ak + 1][am] = a0.y;
        As[ak + 2][am] = a0.z; As[ak + 3][am] = a0.w;
        As[ak + 4][am] = a1.x; As[ak + 5][am] = a1.y;
        As[ak + 6][am] = a1.z; As[ak + 7][am] = a1.w;
        {
            int k = k0 + bk;
            float4 b0, b1;
            if (k < 256) {
                const float* src = (jhi ? wi : wr) + (size_t)k * 256 + jj;
                b0 = *(const float4*)(src);
                b1 = *(const float4*)(src + 4);
            } else {
                const float* src = (jhi ? wr : wi) + (size_t)(k - 256) * 256 + jj;
                b0 = *(const float4*)(src);
                b1 = *(const float4*)(src + 4);
                if (!jhi) {
                    b0.x = -b0.x; b0.y = -b0.y; b0.z = -b0.z; b0.w = -b0.w;
                    b1.x = -b1.x; b1.y = -b1.y; b1.z = -b1.z; b1.w = -b1.w;
                }
            }
            *(float4*)&Bs[bk][bj]     = b0;
            *(float4*)&Bs[bk][bj + 4] = b1;
        }
        __syncthreads();
#pragma unroll
        for (int kk = 0; kk < 16; ++kk) {
            float4 av0 = *(const float4*)&As[kk][ty * 8];
            float4 av1 = *(const float4*)&As[kk][ty * 8 + 4];
            float4 bv0 = *(const float4*)&Bs[kk][tx * 8];
            float4 bv1 = *(const float4*)&Bs[kk][tx * 8 + 4];
            float a[8] = {av0.x, av0.y, av0.z, av0.w, av1.x, av1.y, av1.z, av1.w};
            float b[8] = {bv0.x, bv0.y, bv0.z, bv0.w, bv1.x, bv1.y, bv1.z, bv1.w};
#pragma unroll
            for (int r = 0; r < 8; ++r)
#pragma unroll
                for (int c = 0; c < 8; ++c)
                    acc[r][c] = fmaf(a[r], b[c], acc[r][c]);
        }
        __syncthreads();
    }

    const int col0 = bn + tx * 8;
    float bias[8];
#pragma unroll
    for (int c = 0; c < 8; ++c) {
        int j = col0 + c;
        bias[c] = (j < 256) ? br[j] : bi[j - 256];
    }
#pragma unroll
    for (int r = 0; r < 8; ++r) {
        float* yrow = Y + (size_t)(bm + ty * 8 + r) * HD + col0;
        *(float4*)(yrow)     = make_float4(acc[r][0]+bias[0], acc[r][1]+bias[1],
                                           acc[r][2]+bias[2], acc[r][3]+bias[3]);
        *(float4*)(yrow + 4) = make_float4(acc[r][4]+bias[4], acc[r][5]+bias[5],
                                           acc[r][6]+bias[6], acc[r][7]+bias[7]);
    }
}

// ---------------------------------------------------------------------------
// Recurrent scan: 8 clusters x 8 CTAs x 256 threads.
// Decentralized per-warp broadcast: each warp stages its 32B slice, syncwarp,
// then lanes 0-7 EACH issue one 32B cp.async.bulk to a different peer CTA
// (parallel issue, no CTA barrier). Barrier: count=1, expect 2048B/phase
// (= 8 CTAs x 8 warps x 32B), re-armed by warp 0 after its wait.
// ---------------------------------------------------------------------------
__global__ void __cluster_dims__(8, 1, 1) __launch_bounds__(256, 1)
scan_kernel(const float* __restrict__ wx,
            const float* __restrict__ ur, const float* __restrict__ ui,
            const float* __restrict__ ubr, const float* __restrict__ ubi,
            float* __restrict__ out)
{
    __shared__ float hbuf[2][HD];                       // 2 x 2048 B
    __shared__ __align__(16) float stage[64];           // this CTA's slice
    __shared__ __align__(8) unsigned long long mbar[2];

    unsigned rank;
    asm("mov.u32 %0, %%cluster_ctarank;" : "=r"(rank));
    const int b    = blockIdx.x >> 3;
    const int tid  = threadIdx.x;
    const int lane = tid & 31;
    const int wrp  = tid >> 5;       // warp 0..7
    const int jg   = tid >> 4;
    const int kg   = tid & 15;
    const int j0   = (int)rank * 64 + jg * 4;
    const int jj   = j0 & 255;
    const bool jhi = j0 >= 256;

    const unsigned hb_u32 = su32(&hbuf[0][0]);
    const unsigned st_u32 = su32(&stage[0]);
    const unsigned mb_u32 = su32(&mbar[0]);

    if (tid == 0) {
        asm volatile("mbarrier.init.shared.b64 [%0], %1;" :: "r"(mb_u32),     "r"(1u) : "memory");
        asm volatile("mbarrier.init.shared.b64 [%0], %1;" :: "r"(mb_u32 + 8), "r"(1u) : "memory");
        asm volatile("mbarrier.arrive.expect_tx.shared::cta.b64 _, [%0], %1;"
                     :: "r"(mb_u32),     "r"(2048u) : "memory");
        asm volatile("mbarrier.arrive.expect_tx.shared::cta.b64 _, [%0], %1;"
                     :: "r"(mb_u32 + 8), "r"(2048u) : "memory");
    }
    __syncthreads();
    asm volatile("barrier.cluster.arrive.aligned;" ::: "memory");
    asm volatile("barrier.cluster.wait.aligned;"   ::: "memory");

    // per-lane peer addresses (only lanes 0-7 use them)
    unsigned dsth_l, dstm_l;
    {
        const int d = lane & 7;
        asm("mapa.shared::cluster.u32 %0, %1, %2;" : "=r"(dsth_l) : "r"(hb_u32), "r"(d));
        asm("mapa.shared::cluster.u32 %0, %1, %2;" : "=r"(dstm_l) : "r"(mb_u32), "r"(d));
    }
    // each warp sends the 32B at stage[wrp*8], landing at peer hbuf + rank*256 + wrp*32
    const unsigned src_w = st_u32 + (unsigned)(wrp * 32);
    const unsigned dst_w = dsth_l + (unsigned)(rank * 256 + wrp * 32);

    // ---- weight slice into registers, packed f32x2 along k ----
    unsigned long long w2[4][16];
#pragma unroll
    for (int q = 0; q < 8; ++q) {
        const int k = q * 64 + kg * 4;
        float4 r0, r1, r2, r3;
        if (k < 256) {
            const float* src = (jhi ? ui : ur) + (size_t)k * 256 + jj;
            r0 = *(const float4*)(src);
            r1 = *(const float4*)(src + 256);
            r2 = *(const float4*)(src + 512);
            r3 = *(const float4*)(src + 768);
        } else {
            const float* src = (jhi ? ur : ui) + (size_t)(k - 256) * 256 + jj;
            const float s = jhi ? 1.f : -1.f;
            r0 = *(const float4*)(src);
            r1 = *(const float4*)(src + 256);
            r2 = *(const float4*)(src + 512);
            r3 = *(const float4*)(src + 768);
            r0.x *= s; r0.y *= s; r0.z *= s; r0.w *= s;
            r1.x *= s; r1.y *= s; r1.z *= s; r1.w *= s;
            r2.x *= s; r2.y *= s; r2.z *= s; r2.w *= s;
            r3.x *= s; r3.y *= s; r3.z *= s; r3.w *= s;
        }
        w2[0][2*q]   = packf2(r0.x, r1.x);
        w2[1][2*q]   = packf2(r0.y, r1.y);
        w2[2][2*q]   = packf2(r0.z, r1.z);
        w2[3][2*q]   = packf2(r0.w, r1.w);
        w2[0][2*q+1] = packf2(r2.x, r3.x);
        w2[1][2*q+1] = packf2(r2.y, r3.y);
        w2[2][2*q+1] = packf2(r2.z, r3.z);
        w2[3][2*q+1] = packf2(r2.w, r3.w);
    }
    const float4 ub = jhi ? *(const float4*)(ubi + jj)
                          : *(const float4*)(ubr + jj);

    const float* wx_b  = wx  + (size_t)b * (T_LEN * HD);
    float*       out_b = out + (size_t)b * (T_LEN * HD);

    // ---- t = 0 (h_prev = 0) ----
    {
        float4 wv = *(const float4*)(wx_b + j0);
        float4 yv;
        yv.x = fast_tanh(wv.x + ub.x);
        yv.y = fast_tanh(wv.y + ub.y);
        yv.z = fast_tanh(wv.z + ub.z);
        yv.w = fast_tanh(wv.w + ub.w);
        if ((lane & 15) == 0) *(float4*)&stage[jg * 4] = yv;
        if ((lane & 15) == 8) *(float4*)(out_b + j0) = yv;
        __syncwarp();
        if (lane < 8) {
            asm volatile("fence.proxy.async.shared::cta;" ::: "memory");
            asm volatile(
                "cp.async.bulk.shared::cluster.shared::cta.mbarrier::complete_tx::bytes "
                "[%0], [%1], %2, [%3];"
                :: "r"(dst_w), "r"(src_w), "r"(32u), "r"(dstm_l)
                : "memory");
        }
    }

    for (int t = 1; t < T_LEN; ++t) {
        float4 wv = *(const float4*)(wx_b + (size_t)t * HD + j0);

        const int use  = t - 1;
        const int rbuf = use & 1;
        mbar_wait(mb_u32 + rbuf * 8, (unsigned)((use >> 1) & 1));

        // warp 0 re-arms this buffer's next phase BEFORE its own send below
        if (tid == 0) {
            asm volatile("mbarrier.arrive.expect_tx.shared::cta.b64 _, [%0], %1;"
                         :: "r"(mb_u32 + rbuf * 8), "r"(2048u) : "memory");
        }

        unsigned long long h2[16];
        const float* hp = &hbuf[rbuf][0];
#pragma unroll
        for (int q = 0; q < 8; ++q) {
            ulonglong2 v = *(const ulonglong2*)(hp + q * 64 + kg * 4);
            h2[2*q]   = v.x;
            h2[2*q+1] = v.y;
        }

        unsigned long long acc0 = 0, acc1 = 0, acc2 = 0, acc3 = 0;
#pragma unroll
        for (int q = 0; q < 16; ++q) {
            asm("fma.rn.f32x2 %0, %1, %2, %0;" : "+l"(acc0) : "l"(h2[q]), "l"(w2[0][q]));
            asm("fma.rn.f32x2 %0, %1, %2, %0;" : "+l"(acc1) : "l"(h2[q]), "l"(w2[1][q]));
            asm("fma.rn.f32x2 %0, %1, %2, %0;" : "+l"(acc2) : "l"(h2[q]), "l"(w2[2][q]));
            asm("fma.rn.f32x2 %0, %1, %2, %0;" : "+l"(acc3) : "l"(h2[q]), "l"(w2[3][q]));
        }
        float a0, a1, a2, a3, hq;
        unpackf2(acc0, a0, hq); a0 += hq;
        unpackf2(acc1, a1, hq); a1 += hq;
        unpackf2(acc2, a2, hq); a2 += hq;
        unpackf2(acc3, a3, hq); a3 += hq;
#pragma unroll
        for (int off = 1; off < 16; off <<= 1) {
            a0 += __shfl_xor_sync(0xffffffffu, a0, off);
            a1 += __shfl_xor_sync(0xffffffffu, a1, off);
            a2 += __shfl_xor_sync(0xffffffffu, a2, off);
            a3 += __shfl_xor_sync(0xffffffffu, a3, off);
        }

        float4 yv;
        yv.x = fast_tanh(wv.x + ub.x + a0);
        yv.y = fast_tanh(wv.y + ub.y + a1);
        yv.z = fast_tanh(wv.z + ub.z + a2);
        yv.w = fast_tanh(wv.w + ub.w + a3);

        if (t < T_LEN - 1) {
            // per-warp decentralized broadcast (critical path)
            if ((lane & 15) == 0) *(float4*)&stage[jg * 4] = yv;
            __syncwarp();
            if (lane < 8) {
                const unsigned boff = (unsigned)((t & 1) * 2048);
                const unsigned moff = (unsigned)((t & 1) * 8);
                asm volatile("fence.proxy.async.shared::cta;" ::: "memory");
                asm volatile(
                    "cp.async.bulk.shared::cluster.shared::cta.mbarrier::complete_tx::bytes "
                    "[%0], [%1], %2, [%3];"
                    :: "r"(dst_w + boff), "r"(src_w), "r"(32u), "r"(dstm_l + moff)
                    : "memory");
            }
        }
        if ((lane & 15) == 8) *(float4*)(out_b + (size_t)t * HD + j0) = yv;
    }

    asm volatile("barrier.cluster.arrive.aligned;" ::: "memory");
    asm volatile("barrier.cluster.wait.aligned;"   ::: "memory");
}

// ---------------------------------------------------------------------------
extern "C" void kernel_launch(void* const* d_in, const int* in_sizes, int n_in,
                              void* d_out, int out_size)
{
    const float* x      = (const float*)d_in[0];
    const float* l0_wr  = (const float*)d_in[1];
    const float* l0_wi  = (const float*)d_in[2];
    const float* l0_wbr = (const float*)d_in[3];
    const float* l0_wbi = (const float*)d_in[4];
    const float* l0_ur  = (const float*)d_in[5];
    const float* l0_ui  = (const float*)d_in[6];
    const float* l0_ubr = (const float*)d_in[7];
    const float* l0_ubi = (const float*)d_in[8];
    const float* l1_wr  = (const float*)d_in[9];
    const float* l1_wi  = (const float*)d_in[10];
    const float* l1_wbr = (const float*)d_in[11];
    const float* l1_wbi = (const float*)d_in[12];
    const float* l1_ur  = (const float*)d_in[13];
    const float* l1_ui  = (const float*)d_in[14];
    const float* l1_ubr = (const float*)d_in[15];
    const float* l1_ubi = (const float*)d_in[16];

    float* out = (float*)d_out;

    void *p_wx_v = nullptr, *p_h0_v = nullptr;
    cudaGetSymbolAddress(&p_wx_v, g_wx);
    cudaGetSymbolAddress(&p_h0_v, g_h0);
    float* p_wx = (float*)p_wx_v;
    float* p_h0 = (float*)p_h0_v;

    dim3 pgrid(NROWS / 128, HD / 128);

    proj_kernel<<<pgrid, 256>>>(x, l0_wr, l0_wi, l0_wbr, l0_wbi, p_wx);
    scan_kernel<<<64, 256>>>(p_wx, l0_ur, l0_ui, l0_ubr, l0_ubi, p_h0);
    proj_kernel<<<pgrid, 256>>>(p_h0, l1_wr, l1_wi, l1_wbr, l1_wbi, p_wx);
    scan_kernel<<<64, 256>>>(p_wx, l1_ur, l1_ui, l1_ubr, l1_ubi, out);
}

// round 9
// speedup vs baseline: 1.3473x; 1.2647x over previous
#include <cuda_runtime.h>
#include <cstddef>

#define BATCH   8
#define T_LEN   4096
#define HC      256
#define HD      512
#define NROWS   (BATCH * T_LEN)

__device__ float g_wx[NROWS * HD];   // input-projection output
__device__ float g_h0[NROWS * HD];   // layer-0 hidden states

// ---------------------------------------------------------------- helpers
static __device__ __forceinline__ unsigned su32(const void* p) {
    return (unsigned)__cvta_generic_to_shared(p);
}
static __device__ __forceinline__ unsigned long long packf2(float lo, float hi) {
    unsigned long long r;
    asm("mov.b64 %0, {%1, %2};" : "=l"(r) : "f"(lo), "f"(hi));
    return r;
}
static __device__ __forceinline__ void unpackf2(unsigned long long v, float& lo, float& hi) {
    asm("mov.b64 {%0, %1}, %2;" : "=f"(lo), "=f"(hi) : "l"(v));
}
static __device__ __forceinline__ float hw_tanh(float x) {
    float y;
    asm("tanh.approx.f32 %0, %1;" : "=f"(y) : "f"(x));
    return y;
}
static __device__ __forceinline__ void mbar_wait(unsigned addr, unsigned parity) {
    asm volatile(
        "{\n\t.reg .pred P;\n"
        "LW_%=:\n\t"
        "mbarrier.try_wait.parity.acquire.cluster.shared::cta.b64 P, [%0], %1, 0x989680;\n\t"
        "@P bra LD_%=;\n\t"
        "bra LW_%=;\n"
        "LD_%=:\n\t}"
        :: "r"(addr), "r"(parity) : "memory");
}

// ---------------------------------------------------------------------------
// Projection GEMM (unchanged): Y[N,512] = X[N,512] @ Mw[512,512] + bias
// ---------------------------------------------------------------------------
__global__ __launch_bounds__(256) void proj_kernel(
    const float* __restrict__ X,
    const float* __restrict__ wr, const float* __restrict__ wi,
    const float* __restrict__ br, const float* __restrict__ bi,
    float* __restrict__ Y)
{
    __shared__ float As[16][132];
    __shared__ float Bs[16][132];

    const int bm  = blockIdx.x * 128;
    const int bn  = blockIdx.y * 128;
    const int tid = threadIdx.x;
    const int tx  = tid & 15;
    const int ty  = tid >> 4;
    const int am  = tid >> 1;
    const int ak  = (tid & 1) * 8;
    const int bk  = tid >> 4;
    const int bj  = (tid & 15) * 8;
    const bool jhi = (bn + bj) >= 256;
    const int  jj  = (bn + bj) & 255;

    float acc[8][8];
#pragma unroll
    for (int r = 0; r < 8; ++r)
#pragma unroll
        for (int c = 0; c < 8; ++c) acc[r][c] = 0.f;

    for (int k0 = 0; k0 < HD; k0 += 16) {
        const float* xrow = X + (size_t)(bm + am) * HD + k0 + ak;
        float4 a0 = *(const float4*)(xrow);
        float4 a1 = *(const float4*)(xrow + 4);
        As[ak + 0][am] = a0.x; As[ak + 1][am] = a0.y;
        As[ak + 2][am] = a0.z; As[ak + 3][am] = a0.w;
        As[ak + 4][am] = a1.x; As[ak + 5][am] = a1.y;
        As[ak + 6][am] = a1.z; As[ak + 7][am] = a1.w;
        {
            int k = k0 + bk;
            float4 b0, b1;
            if (k < 256) {
                const float* src = (jhi ? wi : wr) + (size_t)k * 256 + jj;
                b0 = *(const float4*)(src);
                b1 = *(const float4*)(src + 4);
            } else {
                const float* src = (jhi ? wr : wi) + (size_t)(k - 256) * 256 + jj;
                b0 = *(const float4*)(src);
                b1 = *(const float4*)(src + 4);
                if (!jhi) {
                    b0.x = -b0.x; b0.y = -b0.y; b0.z = -b0.z; b0.w = -b0.w;
                    b1.x = -b1.x; b1.y = -b1.y; b1.z = -b1.z; b1.w = -b1.w;
                }
            }
            *(float4*)&Bs[bk][bj]     = b0;
            *(float4*)&Bs[bk][bj + 4] = b1;
        }
        __syncthreads();
#pragma unroll
        for (int kk = 0; kk < 16; ++kk) {
            float4 av0 = *(const float4*)&As[kk][ty * 8];
            float4 av1 = *(const float4*)&As[kk][ty * 8 + 4];
            float4 bv0 = *(const float4*)&Bs[kk][tx * 8];
            float4 bv1 = *(const float4*)&Bs[kk][tx * 8 + 4];
            float a[8] = {av0.x, av0.y, av0.z, av0.w, av1.x, av1.y, av1.z, av1.w};
            float b[8] = {bv0.x, bv0.y, bv0.z, bv0.w, bv1.x, bv1.y, bv1.z, bv1.w};
#pragma unroll
            for (int r = 0; r < 8; ++r)
#pragma unroll
                for (int c = 0; c < 8; ++c)
                    acc[r][c] = fmaf(a[r], b[c], acc[r][c]);
        }
        __syncthreads();
    }

    const int col0 = bn + tx * 8;
    float bias[8];
#pragma unroll
    for (int c = 0; c < 8; ++c) {
        int j = col0 + c;
        bias[c] = (j < 256) ? br[j] : bi[j - 256];
    }
#pragma unroll
    for (int r = 0; r < 8; ++r) {
        float* yrow = Y + (size_t)(bm + ty * 8 + r) * HD + col0;
        *(float4*)(yrow)     = make_float4(acc[r][0]+bias[0], acc[r][1]+bias[1],
                                           acc[r][2]+bias[2], acc[r][3]+bias[3]);
        *(float4*)(yrow + 4) = make_float4(acc[r][4]+bias[4], acc[r][5]+bias[5],
                                           acc[r][6]+bias[6], acc[r][7]+bias[7]);
    }
}

// ---------------------------------------------------------------------------
// Recurrent scan: 8 clusters x 8 CTAs x 256 threads (R4 topology).
// Per step: compute -> stage (256B) -> __syncthreads -> lanes 0-7 of warp 0
// each issue ONE 256B cp.async.bulk to peer (lane&7) in a single warp-wide
// dispatch. Barrier count=1, expect 2048B/phase, re-armed by tid0.
// tanh via MUFU.TANH; bias pre-added before the wait.
// ---------------------------------------------------------------------------
__global__ void __cluster_dims__(8, 1, 1) __launch_bounds__(256, 1)
scan_kernel(const float* __restrict__ wx,
            const float* __restrict__ ur, const float* __restrict__ ui,
            const float* __restrict__ ubr, const float* __restrict__ ubi,
            float* __restrict__ out)
{
    __shared__ float hbuf[2][HD];                       // 2 x 2048 B
    __shared__ __align__(16) float stage[64];           // this CTA's slice
    __shared__ __align__(8) unsigned long long mbar[2];

    unsigned rank;
    asm("mov.u32 %0, %%cluster_ctarank;" : "=r"(rank));
    const int b    = blockIdx.x >> 3;
    const int tid  = threadIdx.x;
    const int lane = tid & 31;
    const int jg   = tid >> 4;
    const int kg   = tid & 15;
    const int j0   = (int)rank * 64 + jg * 4;
    const int jj   = j0 & 255;
    const bool jhi = j0 >= 256;

    const unsigned hb_u32 = su32(&hbuf[0][0]);
    const unsigned st_u32 = su32(&stage[0]);
    const unsigned mb_u32 = su32(&mbar[0]);

    if (tid == 0) {
        asm volatile("mbarrier.init.shared.b64 [%0], %1;" :: "r"(mb_u32),     "r"(1u) : "memory");
        asm volatile("mbarrier.init.shared.b64 [%0], %1;" :: "r"(mb_u32 + 8), "r"(1u) : "memory");
        asm volatile("mbarrier.arrive.expect_tx.shared::cta.b64 _, [%0], %1;"
                     :: "r"(mb_u32),     "r"(2048u) : "memory");
        asm volatile("mbarrier.arrive.expect_tx.shared::cta.b64 _, [%0], %1;"
                     :: "r"(mb_u32 + 8), "r"(2048u) : "memory");
    }
    __syncthreads();
    asm volatile("barrier.cluster.arrive.aligned;" ::: "memory");
    asm volatile("barrier.cluster.wait.aligned;"   ::: "memory");

    // per-lane peer addresses: thread tid<8 sends to peer tid
    unsigned dsth_l, dstm_l;
    {
        const int d = tid & 7;
        asm("mapa.shared::cluster.u32 %0, %1, %2;" : "=r"(dsth_l) : "r"(hb_u32), "r"(d));
        asm("mapa.shared::cluster.u32 %0, %1, %2;" : "=r"(dstm_l) : "r"(mb_u32), "r"(d));
    }
    const unsigned dst_slot = dsth_l + (unsigned)(rank * 256);

    // ---- weight slice into registers, packed f32x2 along k ----
    unsigned long long w2[4][16];
#pragma unroll
    for (int q = 0; q < 8; ++q) {
        const int k = q * 64 + kg * 4;
        float4 r0, r1, r2, r3;
        if (k < 256) {
            const float* src = (jhi ? ui : ur) + (size_t)k * 256 + jj;
            r0 = *(const float4*)(src);
            r1 = *(const float4*)(src + 256);
            r2 = *(const float4*)(src + 512);
            r3 = *(const float4*)(src + 768);
        } else {
            const float* src = (jhi ? ur : ui) + (size_t)(k - 256) * 256 + jj;
            const float s = jhi ? 1.f : -1.f;
            r0 = *(const float4*)(src);
            r1 = *(const float4*)(src + 256);
            r2 = *(const float4*)(src + 512);
            r3 = *(const float4*)(src + 768);
            r0.x *= s; r0.y *= s; r0.z *= s; r0.w *= s;
            r1.x *= s; r1.y *= s; r1.z *= s; r1.w *= s;
            r2.x *= s; r2.y *= s; r2.z *= s; r2.w *= s;
            r3.x *= s; r3.y *= s; r3.z *= s; r3.w *= s;
        }
        w2[0][2*q]   = packf2(r0.x, r1.x);
        w2[1][2*q]   = packf2(r0.y, r1.y);
        w2[2][2*q]   = packf2(r0.z, r1.z);
        w2[3][2*q]   = packf2(r0.w, r1.w);
        w2[0][2*q+1] = packf2(r2.x, r3.x);
        w2[1][2*q+1] = packf2(r2.y, r3.y);
        w2[2][2*q+1] = packf2(r2.z, r3.z);
        w2[3][2*q+1] = packf2(r2.w, r3.w);
    }
    const float4 ub = jhi ? *(const float4*)(ubi + jj)
                          : *(const float4*)(ubr + jj);

    const float* wx_b  = wx  + (size_t)b * (T_LEN * HD);
    float*       out_b = out + (size_t)b * (T_LEN * HD);

    const bool is_stage_lane = ((lane & 15) == 0);
    const bool is_out_lane   = ((lane & 15) == 8);

    // ---- t = 0 (h_prev = 0) ----
    {
        float4 wv = *(const float4*)(wx_b + j0);
        wv.x += ub.x; wv.y += ub.y; wv.z += ub.z; wv.w += ub.w;
        if (is_stage_lane | is_out_lane) {
            float4 yv;
            yv.x = hw_tanh(wv.x);
            yv.y = hw_tanh(wv.y);
            yv.z = hw_tanh(wv.z);
            yv.w = hw_tanh(wv.w);
            if (is_stage_lane) *(float4*)&stage[jg * 4] = yv;
            else               *(float4*)(out_b + j0) = yv;
        }
        __syncthreads();
        if (tid < 8) {
            asm volatile("fence.proxy.async.shared::cta;" ::: "memory");
            asm volatile(
                "cp.async.bulk.shared::cluster.shared::cta.mbarrier::complete_tx::bytes "
                "[%0], [%1], %2, [%3];"
                :: "r"(dst_slot), "r"(st_u32), "r"(256u), "r"(dstm_l)
                : "memory");
        }
    }

    for (int t = 1; t < T_LEN; ++t) {
        float4 wv = *(const float4*)(wx_b + (size_t)t * HD + j0);
        wv.x += ub.x; wv.y += ub.y; wv.z += ub.z; wv.w += ub.w;

        const int use  = t - 1;
        const int rbuf = use & 1;
        mbar_wait(mb_u32 + rbuf * 8, (unsigned)((use >> 1) & 1));

        // re-arm this buffer's next phase (precedes warp 0's send below)
        if (tid == 0) {
            asm volatile("mbarrier.arrive.expect_tx.shared::cta.b64 _, [%0], %1;"
                         :: "r"(mb_u32 + rbuf * 8), "r"(2048u) : "memory");
        }

        unsigned long long h2[16];
        const float* hp = &hbuf[rbuf][0];
#pragma unroll
        for (int q = 0; q < 8; ++q) {
            ulonglong2 v = *(const ulonglong2*)(hp + q * 64 + kg * 4);
            h2[2*q]   = v.x;
            h2[2*q+1] = v.y;
        }

        unsigned long long acc0 = 0, acc1 = 0, acc2 = 0, acc3 = 0;
#pragma unroll
        for (int q = 0; q < 16; ++q) {
            asm("fma.rn.f32x2 %0, %1, %2, %0;" : "+l"(acc0) : "l"(h2[q]), "l"(w2[0][q]));
            asm("fma.rn.f32x2 %0, %1, %2, %0;" : "+l"(acc1) : "l"(h2[q]), "l"(w2[1][q]));
            asm("fma.rn.f32x2 %0, %1, %2, %0;" : "+l"(acc2) : "l"(h2[q]), "l"(w2[2][q]));
            asm("fma.rn.f32x2 %0, %1, %2, %0;" : "+l"(acc3) : "l"(h2[q]), "l"(w2[3][q]));
        }
        float a0, a1, a2, a3, hq;
        unpackf2(acc0, a0, hq); a0 += hq;
        unpackf2(acc1, a1, hq); a1 += hq;
        unpackf2(acc2, a2, hq); a2 += hq;
        unpackf2(acc3, a3, hq); a3 += hq;
#pragma unroll
        for (int off = 1; off < 16; off <<= 1) {
            a0 += __shfl_xor_sync(0xffffffffu, a0, off);
            a1 += __shfl_xor_sync(0xffffffffu, a1, off);
            a2 += __shfl_xor_sync(0xffffffffu, a2, off);
            a3 += __shfl_xor_sync(0xffffffffu, a3, off);
        }

        if (is_stage_lane | is_out_lane) {
            float4 yv;
            yv.x = hw_tanh(wv.x + a0);
            yv.y = hw_tanh(wv.y + a1);
            yv.z = hw_tanh(wv.z + a2);
            yv.w = hw_tanh(wv.w + a3);
            if (is_stage_lane) {
                if (t < T_LEN - 1) *(float4*)&stage[jg * 4] = yv;
            } else {
                *(float4*)(out_b + (size_t)t * HD + j0) = yv;
            }
        }

        if (t < T_LEN - 1) {
            __syncthreads();
            if (tid < 8) {
                const unsigned boff = (unsigned)((t & 1) * 2048);
                const unsigned moff = (unsigned)((t & 1) * 8);
                asm volatile("fence.proxy.async.shared::cta;" ::: "memory");
                asm volatile(
                    "cp.async.bulk.shared::cluster.shared::cta.mbarrier::complete_tx::bytes "
                    "[%0], [%1], %2, [%3];"
                    :: "r"(dst_slot + boff), "r"(st_u32), "r"(256u), "r"(dstm_l + moff)
                    : "memory");
            }
        }
    }

    asm volatile("barrier.cluster.arrive.aligned;" ::: "memory");
    asm volatile("barrier.cluster.wait.aligned;"   ::: "memory");
}

// ---------------------------------------------------------------------------
extern "C" void kernel_launch(void* const* d_in, const int* in_sizes, int n_in,
                              void* d_out, int out_size)
{
    const float* x      = (const float*)d_in[0];
    const float* l0_wr  = (const float*)d_in[1];
    const float* l0_wi  = (const float*)d_in[2];
    const float* l0_wbr = (const float*)d_in[3];
    const float* l0_wbi = (const float*)d_in[4];
    const float* l0_ur  = (const float*)d_in[5];
    const float* l0_ui  = (const float*)d_in[6];
    const float* l0_ubr = (const float*)d_in[7];
    const float* l0_ubi = (const float*)d_in[8];
    const float* l1_wr  = (const float*)d_in[9];
    const float* l1_wi  = (const float*)d_in[10];
    const float* l1_wbr = (const float*)d_in[11];
    const float* l1_wbi = (const float*)d_in[12];
    const float* l1_ur  = (const float*)d_in[13];
    const float* l1_ui  = (const float*)d_in[14];
    const float* l1_ubr = (const float*)d_in[15];
    const float* l1_ubi = (const float*)d_in[16];

    float* out = (float*)d_out;

    void *p_wx_v = nullptr, *p_h0_v = nullptr;
    cudaGetSymbolAddress(&p_wx_v, g_wx);
    cudaGetSymbolAddress(&p_h0_v, g_h0);
    float* p_wx = (float*)p_wx_v;
    float* p_h0 = (float*)p_h0_v;

    dim3 pgrid(NROWS / 128, HD / 128);

    proj_kernel<<<pgrid, 256>>>(x, l0_wr, l0_wi, l0_wbr, l0_wbi, p_wx);
    scan_kernel<<<64, 256>>>(p_wx, l0_ur, l0_ui, l0_ubr, l0_ubi, p_h0);
    proj_kernel<<<pgrid, 256>>>(p_h0, l1_wr, l1_wi, l1_wbr, l1_wbi, p_wx);
    scan_kernel<<<64, 256>>>(p_wx, l1_ur, l1_ui, l1_ubr, l1_ubi, out);
}